// round 7
// baseline (speedup 1.0000x reference)
#include <cuda_runtime.h>

// Problem: bidirectional LSTM encoder. B=128, T=512, V=32000, E=256, H=128, 4H=512
// Inputs: tokens[B,T] (int32 or int64 - runtime detected), emb[V,E] f32,
//   W_fw[E,4H], U_fw[H,4H], b_fw[4H], W_bw, U_bw, b_bw
// Output (flattened): out[B,T,2H], h_fw[B,H], c_fw[B,H], h_bw[B,H], c_bw[B,H]

typedef unsigned long long u64;
typedef unsigned int u32;

// -------- device scratch (static: no runtime allocation allowed) ----------
__device__ float g_P[32000 * 1024];        // emb @ [W_fw|W_bw] + bias  (131 MB)
__device__ int g_tok64;                    // 1 if tokens are int64

// -------- f32x2 helpers ---------------------------------------------------
__device__ __forceinline__ u64 dup2f(float x) {
    u64 r; asm("mov.b64 %0, {%1, %1};" : "=l"(r) : "f"(x)); return r;
}
__device__ __forceinline__ u64 pack2f(float lo, float hi) {
    u64 r; asm("mov.b64 %0, {%1, %2};" : "=l"(r) : "f"(lo), "f"(hi)); return r;
}
__device__ __forceinline__ void ffma2(u64& d, u64 a, u64 b) {
    asm("fma.rn.f32x2 %0, %1, %2, %0;" : "+l"(d) : "l"(a), "l"(b));
}
__device__ __forceinline__ float2 unpk(u64 v) {
    float lo, hi; asm("mov.b64 {%0, %1}, %2;" : "=f"(lo), "=f"(hi) : "l"(v));
    float2 r; r.x = lo; r.y = hi; return r;
}
__device__ __forceinline__ u32 smem_u32(const void* p) {
    u32 a;
    asm("{ .reg .u64 t; cvta.to.shared.u64 t, %1; cvt.u32.u64 %0, t; }"
        : "=r"(a) : "l"(p));
    return a;
}
// DSMEM scatter: store v to the same smem offset in cluster CTA `rank`
__device__ __forceinline__ void st_cluster_f32(u32 laddr, int rank, float v) {
    asm volatile(
        "{ .reg .b32 ra;\n\t"
        "mapa.shared::cluster.u32 ra, %0, %1;\n\t"
        "st.shared::cluster.f32 [ra], %2; }"
        :: "r"(laddr), "r"(rank), "f"(v) : "memory");
}
__device__ __forceinline__ void cluster_sync_() {
    asm volatile("barrier.cluster.arrive.aligned;" ::: "memory");
    asm volatile("barrier.cluster.wait.aligned;" ::: "memory");
}

// fast gates: |z| bounded here (~30) so __expf never overflows for sigmoid;
// tanh uses the sign-safe form to avoid inf/inf.
__device__ __forceinline__ float fsigmoid(float x) {
    return 1.0f / (1.0f + __expf(-x));
}
__device__ __forceinline__ float ftanh_(float x) {
    float e = __expf(-2.0f * fabsf(x));
    float r = (1.0f - e) / (1.0f + e);
    return copysignf(r, x);
}

// -------- token dtype detection ------------------------------------------
// int64 layout: every odd 32-bit word (high half) is 0 (tokens in [0,32000)).
__global__ void detect_tok_kernel(const u32* __restrict__ tp) {
    if (threadIdx.x == 0) {
        int nz = 0;
        for (int i = 0; i < 128; ++i) nz += (tp[2 * i + 1] != 0u);
        g_tok64 = (nz == 0) ? 1 : 0;
    }
}

// -------- projection GEMM: P[v,n] = sum_k emb[v,k]*Wcat[k,n] + bcat[n] ----
// M=32000, N=1024 (0..511 fw, 512..1023 bw), K=256
// BM=128, BN=128, BK=16; 256 threads; thread tile 8m x 8n, n FINE-GRAINED:
// thread (tx,ty) owns cols {tx+16j} -> B reads are stride-1 LDS.64 across
// lanes (conflict-free), A reads are half-warp broadcasts.
__global__ __launch_bounds__(256) void proj_kernel(
    const float* __restrict__ emb,
    const float* __restrict__ Wf, const float* __restrict__ Wb,
    const float* __restrict__ bf, const float* __restrict__ bbias)
{
    __shared__ __align__(16) float As[16][132];   // transposed: As[k][m]
    __shared__ __align__(16) u64   Bs[16][128];   // dup-packed: Bs[k][n] = (w,w)

    const int tid = threadIdx.x;
    const int M0 = blockIdx.y * 128;
    const int N0 = blockIdx.x * 128;
    const int tx = tid & 15;          // fine col: n = tx + 16j
    const int ty = tid >> 4;          // m group: rows 8*ty..8*ty+7
    const int ar = tid >> 1;
    const int ak = (tid & 1) * 8;
    const int br = tid >> 4;
    const int bc = (tid & 15) * 8;

    const int ncol = N0 + bc;
    const float* wsrc = (ncol < 512) ? (Wf + ncol) : (Wb + (ncol - 512));

    u64 acc[4][8];
    #pragma unroll
    for (int i = 0; i < 4; ++i)
        #pragma unroll
        for (int j = 0; j < 8; ++j) acc[i][j] = 0ull;

    for (int kt = 0; kt < 256; kt += 16) {
        const float4* ap = (const float4*)(emb + (size_t)(M0 + ar) * 256 + kt + ak);
        float4 a0 = ap[0], a1 = ap[1];
        As[ak + 0][ar] = a0.x; As[ak + 1][ar] = a0.y;
        As[ak + 2][ar] = a0.z; As[ak + 3][ar] = a0.w;
        As[ak + 4][ar] = a1.x; As[ak + 5][ar] = a1.y;
        As[ak + 6][ar] = a1.z; As[ak + 7][ar] = a1.w;
        const float* wrow = wsrc + (size_t)(kt + br) * 512;
        float4 bv0 = *(const float4*)(wrow);
        float4 bv1 = *(const float4*)(wrow + 4);
        Bs[br][bc + 0] = dup2f(bv0.x); Bs[br][bc + 1] = dup2f(bv0.y);
        Bs[br][bc + 2] = dup2f(bv0.z); Bs[br][bc + 3] = dup2f(bv0.w);
        Bs[br][bc + 4] = dup2f(bv1.x); Bs[br][bc + 5] = dup2f(bv1.y);
        Bs[br][bc + 6] = dup2f(bv1.z); Bs[br][bc + 7] = dup2f(bv1.w);
        __syncthreads();

        #pragma unroll
        for (int k = 0; k < 16; ++k) {
            const ulonglong2* arp = (const ulonglong2*)&As[k][ty * 8];
            ulonglong2 am01 = arp[0];
            ulonglong2 am23 = arp[1];
            u64 avv[4] = { am01.x, am01.y, am23.x, am23.y };
            u64 bvv[8];
            #pragma unroll
            for (int j = 0; j < 8; ++j) bvv[j] = Bs[k][tx + 16 * j];
            #pragma unroll
            for (int mi = 0; mi < 4; ++mi)
                #pragma unroll
                for (int ni = 0; ni < 8; ++ni)
                    ffma2(acc[mi][ni], avv[mi], bvv[ni]);
        }
        __syncthreads();
    }

    float bias[8];
    #pragma unroll
    for (int ni = 0; ni < 8; ++ni) {
        int nc = N0 + tx + 16 * ni;
        bias[ni] = (nc < 512) ? bf[nc] : bbias[nc - 512];
    }
    #pragma unroll
    for (int mi = 0; mi < 4; ++mi) {
        size_t row0 = (size_t)(M0 + ty * 8 + 2 * mi) * 1024 + N0 + tx;
        #pragma unroll
        for (int ni = 0; ni < 8; ++ni) {
            float2 p = unpk(acc[mi][ni]);
            g_P[row0 + 16 * ni]        = p.x + bias[ni];
            g_P[row0 + 1024 + 16 * ni] = p.y + bias[ni];
        }
    }
}

// -------- half-CTA named barrier (128 threads; id 1=fw, 2=bw) -------------
__device__ __forceinline__ void bar_half(int dir) {
    asm volatile("bar.sync %0, 128;" :: "r"(dir + 1) : "memory");
}

// -------- persistent bidirectional LSTM recurrence (DSMEM clusters) -------
// 128 CTAs = 16 clusters x 8. Cluster = one batch group (8 b); rank = kg
// (16 hidden indices). Threads 0..127 = forward, 128..255 = backward.
// h exchange: each thread DSMEM-scatters its h value to all 8 ranks'
// double-buffered h_s; one cluster.sync per step replaces the software
// grid barrier AND the L2 staging round trip.
// U lives in registers; dot's only smem reads are warp-uniform broadcasts.
// Per half smem: h_s[2 buf][8 b][128 k] 8KB + z_p[4 w][8 b][64 c] u64 16KB.
#define HALF_BYTES 24576
#define LSTM_SMEM (2 * HALF_BYTES + 16384)

__global__ void __cluster_dims__(8, 1, 1) __launch_bounds__(256)
lstm_kernel(
    const void* __restrict__ tokens,
    const float* __restrict__ Uf, const float* __restrict__ Ub,
    float* __restrict__ out)
{
    extern __shared__ char smem[];
    const int tid = threadIdx.x;
    const int dir = tid >> 7;                // 0 fw, 1 bw
    const int t2 = tid & 127;
    const int w = t2 >> 5;                   // warp-in-half = k segment 0..3
    const int lane = t2 & 31;
    const int bgcta = blockIdx.x >> 3;       // batch group 0..15 (8 b each)
    const int kg = blockIdx.x & 7;           // k group 0..7 = cluster rank

    char* half = smem + dir * HALF_BYTES;
    float* h_buf[2] = { (float*)half, (float*)(half + 4096) };  // [8 b][128 k]
    u64*   z_p = (u64*)(half + 8192);             // [4 w][8 b][64 c] k-pair partials
    int* tok_s = (int*)(smem + 2 * HALF_BYTES);   // [8 b][512 t]

    const float* U = dir ? Ub : Uf;
    const int tok64 = g_tok64;

    // one-time token prefetch (whole CTA): tok_s[b][t]
    for (int i = tid; i < 4096; i += 256) {
        int b = i >> 9, tt = i & 511;
        int idx = (bgcta * 8 + b) * 512 + tt;
        tok_s[i] = tok64 ? (int)((const long long*)tokens)[idx]
                         : ((const int*)tokens)[idx];
    }

    // U slice into registers: thread owns local cols {2*lane, 2*lane+1} over
    // its warp's k segment [32w, 32w+32), packed as k-pairs.
    // local col c -> global col (c>>4)*128 + kg*16 + (c&15)
    const int c0 = 2 * lane;
    const int kb = 32 * w;
    const int col0 = ((c0 >> 4) << 7) + (kg << 4) + (c0 & 15);
    const int col1 = (((c0 + 1) >> 4) << 7) + (kg << 4) + ((c0 + 1) & 15);
    u64 Ur0[16], Ur1[16];
    #pragma unroll
    for (int k2 = 0; k2 < 16; ++k2) {
        int k = kb + 2 * k2;
        Ur0[k2] = pack2f(U[(size_t)k * 512 + col0], U[(size_t)(k + 1) * 512 + col0]);
        Ur1[k2] = pack2f(U[(size_t)k * 512 + col1], U[(size_t)(k + 1) * 512 + col1]);
    }
    __syncthreads();   // tokens visible CTA-wide

    // update mapping
    const int ub = t2 >> 4;                  // 0..7
    const int uk = t2 & 15;                  // 0..15
    const int bglob = bgcta * 8 + ub;
    const int kglob = kg * 16 + uk;
    // DSMEM scatter target offsets (same offset in every rank's smem)
    const u32 hoff[2] = {
        smem_u32(h_buf[0]) + (u32)(ub * 128 + kglob) * 4,
        smem_u32(h_buf[1]) + (u32)(ub * 128 + kglob) * 4
    };

    float creg = 0.f, hlast = 0.f;

    for (int step = 0; step < 512; ++step) {
        const int t = dir ? (511 - step) : step;
        const int rbuf = step & 1;

        // (1) P gather (single LDG layer, hidden under dot)
        const int tk = tok_s[ub * 512 + t];
        const float* Pr = g_P + (size_t)tk * 1024 + dir * 512 + kglob;
        float zg_[4] = { Pr[0], Pr[128], Pr[256], Pr[384] };

        // (2) dot partials: U in regs, h (already local via DSMEM) broadcast
        if (step) {
            const float* h_s = h_buf[rbuf];
            u64 acc0[8], acc1[8];
            #pragma unroll
            for (int b = 0; b < 8; ++b) { acc0[b] = 0ull; acc1[b] = 0ull; }

            #pragma unroll
            for (int k2 = 0; k2 < 16; ++k2) {
                const float* hk = &h_s[kb + 2 * k2];
                u64 u0 = Ur0[k2], u1 = Ur1[k2];
                #pragma unroll
                for (int b = 0; b < 8; ++b) {
                    u64 hb = *(const u64*)&hk[b * 128];
                    ffma2(acc0[b], hb, u0);
                    ffma2(acc1[b], hb, u1);
                }
            }
            // store partials: z_p[w][b][c0..c0+1] -> STS.128 stride-16B (clean)
            #pragma unroll
            for (int b = 0; b < 8; ++b) {
                ulonglong2 v; v.x = acc0[b]; v.y = acc1[b];
                *(ulonglong2*)&z_p[(size_t)(w * 8 + b) * 64 + c0] = v;
            }
        }
        bar_half(dir);

        // (3) update: reduce 4 warps x (lo+hi k-pair) + P, gates, state
        if (step) {
            #pragma unroll
            for (int ws = 0; ws < 4; ++ws) {
                #pragma unroll
                for (int g = 0; g < 4; ++g) {
                    float2 f = unpk(z_p[(size_t)(ws * 8 + ub) * 64 + g * 16 + uk]);
                    zg_[g] += f.x + f.y;
                }
            }
        }
        float ig = fsigmoid(zg_[0]);
        float fg = fsigmoid(zg_[1]);
        float gg = ftanh_(zg_[2]);
        float og = fsigmoid(zg_[3]);
        creg = fg * creg + ig * gg;
        float hv = og * ftanh_(creg);
        hlast = hv;

        out[((size_t)bglob * 512 + t) * 256 + dir * 128 + kglob] = hv;

        // (4) DSMEM scatter h to all 8 cluster ranks' next-step buffer
        {
            const u32 laddr = hoff[rbuf ^ 1];
            #pragma unroll
            for (int r = 0; r < 8; ++r) st_cluster_f32(laddr, r, hv);
        }

        // (5) one HW cluster barrier per step (stateless -> replay-safe);
        // orders the DSMEM stores for next step's dot.
        cluster_sync_();
    }

    // final states: out + [16777216 : h_fw, c_fw, h_bw, c_bw] each [B,H]
    size_t base = (size_t)16777216 + (size_t)dir * 32768;
    out[base + (size_t)bglob * 128 + kglob]         = hlast;
    out[base + 16384 + (size_t)bglob * 128 + kglob] = creg;
}

// -------- entry point ------------------------------------------------------
extern "C" void kernel_launch(void* const* d_in, const int* in_sizes, int n_in,
                              void* d_out, int out_size)
{
    const void*  tokens = d_in[0];
    const float* emb    = (const float*)d_in[1];
    const float* W_fw   = (const float*)d_in[2];
    const float* U_fw   = (const float*)d_in[3];
    const float* b_fw   = (const float*)d_in[4];
    const float* W_bw   = (const float*)d_in[5];
    const float* U_bw   = (const float*)d_in[6];
    const float* b_bw   = (const float*)d_in[7];
    float* out = (float*)d_out;

    (void)in_sizes; (void)n_in; (void)out_size;

    detect_tok_kernel<<<1, 32>>>((const u32*)tokens);

    dim3 pgrid(8, 250);   // N tiles x M tiles
    proj_kernel<<<pgrid, 256>>>(emb, W_fw, W_bw, b_fw, b_bw);

    cudaFuncSetAttribute(lstm_kernel,
                         cudaFuncAttributeMaxDynamicSharedMemorySize, LSTM_SMEM);
    lstm_kernel<<<128, 256, LSTM_SMEM>>>(tokens, U_fw, U_bw, out);
}